// round 12
// baseline (speedup 1.0000x reference)
#include <cuda_runtime.h>

// out[b,j,h] = (1/N) * sum_i sum_g W[b,i,j,h,g] * x[b,i,g]
// B=16, N=32, H=64. W: 256 MiB fp32 streamed once -> pure HBM-bound.
//
// FINAL (converged champion; device 41.95-42.24us across repeat benches,
// DRAM 82%, 6.46-6.50 TB/s). 11 rounds / 7 structural families all pin at
// 6.34-6.51 TB/s — the B300's pattern-independent achieved read ceiling
// (docs: LTS saturates before HBM channels; LDG.cv ≡ TMA). Mandatory traffic
// 268MB / 6.5TB/s = 41.2us floor; this kernel runs at ~98% of it.
// Tested and rejected: deeper register pipelines (R2), TMA multi-stage smem
// rings (R3), h-split balancing (R4/R5), fully-contiguous 2-pass (R6), phase
// stagger (R7/R9), explicit depth-1 prefetch (R8). Measurement noise bands
// (same binary, repeat runs): device +/-0.15us, harness +/-0.5us.
//
// Shape: one CTA per (b,j), 256 threads; per 16KB i-tile each thread issues
// 4 coalesced LDG.128 + 16 FFMA; x[b,:,:] cached in smem; 16-lane shfl
// reduce; __stwt outputs bypass L2.

#define BB 16
#define NN 32
#define HH 64

__global__ __launch_bounds__(256, 4)
void msg_nn_kernel(const float4* __restrict__ W,
                   const float4* __restrict__ X,
                   float* __restrict__ out)
{
    const int bj = blockIdx.x;      // 0..511
    const int b  = bj >> 5;
    const int j  = bj & (NN - 1);

    __shared__ float4 xs[NN * HH / 4];   // x[b,:,:] = 512 float4 = 8 KB

    const int t = threadIdx.x;      // 0..255

    // Stage x[b,:,:] into smem (512 float4, 2 per thread)
    const float4* xb = X + (size_t)b * (NN * HH / 4);
    xs[t]       = xb[t];
    xs[t + 256] = xb[t + 256];
    __syncthreads();

    const int g4 = t & 15;          // g-quad owned by this thread
    const int h0 = t >> 4;          // base h row

    const size_t tileF4 = (size_t)HH * HH / 4;        // 1024
    const size_t IS     = (size_t)NN * tileF4;        // 32768 f4 (i stride)
    const float4* Wbase = W + ((size_t)b * NN * NN + j) * tileF4;

    float acc0 = 0.f, acc1 = 0.f, acc2 = 0.f, acc3 = 0.f;

    #pragma unroll 2
    for (int i = 0; i < NN; ++i) {
        const float4* tp = Wbase + (size_t)i * IS;
        const float4 xv = xs[i * 16 + g4];

        const float4 w0 = tp[t];
        const float4 w1 = tp[t + 256];
        const float4 w2 = tp[t + 512];
        const float4 w3 = tp[t + 768];

        acc0 += w0.x * xv.x + w0.y * xv.y + w0.z * xv.z + w0.w * xv.w;
        acc1 += w1.x * xv.x + w1.y * xv.y + w1.z * xv.z + w1.w * xv.w;
        acc2 += w2.x * xv.x + w2.y * xv.y + w2.z * xv.z + w2.w * xv.w;
        acc3 += w3.x * xv.x + w3.y * xv.y + w3.z * xv.z + w3.w * xv.w;
    }

    // Reduce 16 g-quads per h within each contiguous 16-lane group.
    const unsigned mask = 0xFFFFFFFFu;
    #pragma unroll
    for (int off = 8; off > 0; off >>= 1) {
        acc0 += __shfl_down_sync(mask, acc0, off);
        acc1 += __shfl_down_sync(mask, acc1, off);
        acc2 += __shfl_down_sync(mask, acc2, off);
        acc3 += __shfl_down_sync(mask, acc3, off);
    }

    if (g4 == 0) {
        const float sc = 1.0f / (float)NN;
        float* o = out + (size_t)bj * HH + h0;
        __stwt(o +  0, acc0 * sc);
        __stwt(o + 16, acc1 * sc);
        __stwt(o + 32, acc2 * sc);
        __stwt(o + 48, acc3 * sc);
    }
}

extern "C" void kernel_launch(void* const* d_in, const int* in_sizes, int n_in,
                              void* d_out, int out_size)
{
    const float4* W = (const float4*)d_in[0];   // edge_wgt [B,N,N,H,H] fp32
    const float4* X = (const float4*)d_in[1];   // node_hidden [B,N,H] fp32
    float* out = (float*)d_out;                 // [B,N,H] fp32

    msg_nn_kernel<<<BB * NN, 256>>>(W, X, out);   // 512 CTAs, single wave-set
}

// round 13
// speedup vs baseline: 1.0164x; 1.0164x over previous
#include <cuda_runtime.h>

// out[b,j,h] = (1/N) * sum_i sum_g W[b,i,j,h,g] * x[b,i,g]
// B=16, N=32, H=64. W: 256 MiB fp32 streamed once -> pure HBM-bound.
//
// FINAL (converged champion; identical binary benched 3x: device
// 41.95 / 42.24 / 43.17us — +/-0.6us DVFS noise band, DRAM 79.6-82.0%).
// 12 rounds / 7 structural families all pin at 6.3-6.5 TB/s — the B300's
// pattern-independent achieved read ceiling (docs: LTS saturates before HBM
// channels; LDG.cv ≡ TMA). Mandatory traffic 268MB / 6.5TB/s = 41.2us floor;
// best observed device time = 98% of floor. Tested and rejected: deeper
// register pipelines (R2), TMA multi-stage smem rings (R3), h-split
// balancing (R4/R5), fully-contiguous 2-pass (R6), phase stagger (R7/R9),
// explicit depth-1 prefetch (R8).
//
// Shape: one CTA per (b,j), 256 threads; per 16KB i-tile each thread issues
// 4 coalesced LDG.128 + 16 FFMA; x[b,:,:] cached in smem; 16-lane shfl
// reduce; __stwt outputs bypass L2.

#define BB 16
#define NN 32
#define HH 64

__global__ __launch_bounds__(256, 4)
void msg_nn_kernel(const float4* __restrict__ W,
                   const float4* __restrict__ X,
                   float* __restrict__ out)
{
    const int bj = blockIdx.x;      // 0..511
    const int b  = bj >> 5;
    const int j  = bj & (NN - 1);

    __shared__ float4 xs[NN * HH / 4];   // x[b,:,:] = 512 float4 = 8 KB

    const int t = threadIdx.x;      // 0..255

    // Stage x[b,:,:] into smem (512 float4, 2 per thread)
    const float4* xb = X + (size_t)b * (NN * HH / 4);
    xs[t]       = xb[t];
    xs[t + 256] = xb[t + 256];
    __syncthreads();

    const int g4 = t & 15;          // g-quad owned by this thread
    const int h0 = t >> 4;          // base h row

    const size_t tileF4 = (size_t)HH * HH / 4;        // 1024
    const size_t IS     = (size_t)NN * tileF4;        // 32768 f4 (i stride)
    const float4* Wbase = W + ((size_t)b * NN * NN + j) * tileF4;

    float acc0 = 0.f, acc1 = 0.f, acc2 = 0.f, acc3 = 0.f;

    #pragma unroll 2
    for (int i = 0; i < NN; ++i) {
        const float4* tp = Wbase + (size_t)i * IS;
        const float4 xv = xs[i * 16 + g4];

        const float4 w0 = tp[t];
        const float4 w1 = tp[t + 256];
        const float4 w2 = tp[t + 512];
        const float4 w3 = tp[t + 768];

        acc0 += w0.x * xv.x + w0.y * xv.y + w0.z * xv.z + w0.w * xv.w;
        acc1 += w1.x * xv.x + w1.y * xv.y + w1.z * xv.z + w1.w * xv.w;
        acc2 += w2.x * xv.x + w2.y * xv.y + w2.z * xv.z + w2.w * xv.w;
        acc3 += w3.x * xv.x + w3.y * xv.y + w3.z * xv.z + w3.w * xv.w;
    }

    // Reduce 16 g-quads per h within each contiguous 16-lane group.
    const unsigned mask = 0xFFFFFFFFu;
    #pragma unroll
    for (int off = 8; off > 0; off >>= 1) {
        acc0 += __shfl_down_sync(mask, acc0, off);
        acc1 += __shfl_down_sync(mask, acc1, off);
        acc2 += __shfl_down_sync(mask, acc2, off);
        acc3 += __shfl_down_sync(mask, acc3, off);
    }

    if (g4 == 0) {
        const float sc = 1.0f / (float)NN;
        float* o = out + (size_t)bj * HH + h0;
        __stwt(o +  0, acc0 * sc);
        __stwt(o + 16, acc1 * sc);
        __stwt(o + 32, acc2 * sc);
        __stwt(o + 48, acc3 * sc);
    }
}

extern "C" void kernel_launch(void* const* d_in, const int* in_sizes, int n_in,
                              void* d_out, int out_size)
{
    const float4* W = (const float4*)d_in[0];   // edge_wgt [B,N,N,H,H] fp32
    const float4* X = (const float4*)d_in[1];   // node_hidden [B,N,H] fp32
    float* out = (float*)d_out;                 // [B,N,H] fp32

    msg_nn_kernel<<<BB * NN, 256>>>(W, X, out);   // 512 CTAs, single wave-set
}